// round 1
// baseline (speedup 1.0000x reference)
#include <cuda_runtime.h>
#include <cstdint>

#define NSPAN  256
#define KKNOW  1024
#define DMODEL 512
#define LMAX   64
#define HID    500
#define NPAIR  (NSPAN * (LMAX + 1))   /* 16640 */

// ---------------- scratch (device globals; no allocation) ----------------
__device__ float g_sentinel[NSPAN * DMODEL];
__device__ float g_span_part[NSPAN * DMODEL];   // includes b1, cols [500,512)=0
__device__ float g_know_part[KKNOW * DMODEL];
__device__ float g_sent_part[NSPAN * DMODEL];
__device__ float g_W2p[DMODEL * DMODEL];        // W2 padded 512x512
__device__ float g_b2p[DMODEL];
__device__ float g_w3p[DMODEL];
__device__ float g_scpart[4 * NPAIR];           // per-N-tile score partials

// ---------------- prep: pad W2 / b2 / W3 ----------------
__global__ void prep_kernel(const float* __restrict__ W2,
                            const float* __restrict__ b2,
                            const float* __restrict__ W3) {
    int i = blockIdx.x * blockDim.x + threadIdx.x;   // 0 .. 512*512
    int k = i >> 9, n = i & 511;
    g_W2p[i] = (k < HID && n < HID) ? W2[k * HID + n] : 0.f;
    if (i < DMODEL) {
        g_b2p[i] = (i < HID) ? b2[i] : 0.f;
        g_w3p[i] = (i < HID) ? W3[i] : 0.f;
    }
}

// ---------------- small SGEMM: C[M x 512] = maybe_relu(A[M x 512] @ B[512 x N] + bias)
// 64x64 tile, 128 threads, TM=4 TN=8. Output cols [N,512) zero-filled.
__global__ void __launch_bounds__(128) gemm64_kernel(
    const float* __restrict__ A, const float* __restrict__ B, int ldb,
    const float* __restrict__ bias, float* __restrict__ C,
    int N, int relu) {
    __shared__ float As[16][64];
    __shared__ float Bs[16][64];
    int tid = threadIdx.x;
    int tx = tid & 7, ty = tid >> 3;
    int m0 = blockIdx.y * 64;
    int n0 = blockIdx.x * 64;
    int a_m = tid >> 1, a_k = (tid & 1) * 8;
    int b_k = tid >> 3, b_n = (tid & 7) * 8;

    float acc[4][8];
#pragma unroll
    for (int i = 0; i < 4; i++)
#pragma unroll
        for (int j = 0; j < 8; j++) acc[i][j] = 0.f;

    for (int k0 = 0; k0 < DMODEL; k0 += 16) {
        const float* ap = A + (size_t)(m0 + a_m) * DMODEL + k0 + a_k;
        float4 v0 = *(const float4*)ap;
        float4 v1 = *(const float4*)(ap + 4);
        As[a_k + 0][a_m] = v0.x; As[a_k + 1][a_m] = v0.y;
        As[a_k + 2][a_m] = v0.z; As[a_k + 3][a_m] = v0.w;
        As[a_k + 4][a_m] = v1.x; As[a_k + 5][a_m] = v1.y;
        As[a_k + 6][a_m] = v1.z; As[a_k + 7][a_m] = v1.w;
#pragma unroll
        for (int r = 0; r < 8; r += 4) {
            int n = n0 + b_n + r;
            float4 v = make_float4(0.f, 0.f, 0.f, 0.f);
            if (n < N) v = *(const float4*)(B + (size_t)(k0 + b_k) * ldb + n);
            *(float4*)&Bs[b_k][b_n + r] = v;
        }
        __syncthreads();
#pragma unroll
        for (int kk = 0; kk < 16; kk++) {
            float a[4], b[8];
            *(float4*)&a[0] = *(const float4*)&As[kk][ty * 4];
            *(float4*)&b[0] = *(const float4*)&Bs[kk][tx * 8];
            *(float4*)&b[4] = *(const float4*)&Bs[kk][tx * 8 + 4];
#pragma unroll
            for (int i = 0; i < 4; i++)
#pragma unroll
                for (int j = 0; j < 8; j++) acc[i][j] += a[i] * b[j];
        }
        __syncthreads();
    }
#pragma unroll
    for (int i = 0; i < 4; i++) {
        int m = m0 + ty * 4 + i;
#pragma unroll
        for (int j = 0; j < 8; j++) {
            int n = n0 + tx * 8 + j;
            float v = 0.f;
            if (n < N) {
                v = acc[i][j] + (bias ? bias[n] : 0.f);
                if (relu) v = fmaxf(v, 0.f);
            }
            C[(size_t)m * DMODEL + n] = v;
        }
    }
}

// ---------------- big fused pair GEMM ----------------
// Row p = n*65 + l. A[p][k] = relu(span_part[n][k] + part[k]),
// part = know_part[s2c[n][l]] (l<64) else sent_part[n].
// acc = A @ W2p; epilogue folds relu(acc + b2)·W3 into score partials.
// 128x128 tile, 256 threads, TM=TN=8. grid = (4 N-tiles, 130 M-tiles).
__global__ void __launch_bounds__(256) gemm_pair_kernel(const int* __restrict__ s2c) {
    __shared__ float As[16][128];
    __shared__ float Bs[16][128];
    __shared__ float sred[128][17];
    int tid = threadIdx.x;
    int tx = tid & 15, ty = tid >> 4;
    int m0 = blockIdx.y * 128;
    int n0 = blockIdx.x * 128;
    int a_m = tid >> 2;
    int a_k = (tid & 3) * 4;
    int b_k = tid >> 5;
    int b_n = (tid & 31) * 4;

    const float* base1[2];
    const float* base2[2];
#pragma unroll
    for (int r = 0; r < 2; r++) {
        int p = m0 + a_m + r * 64;
        int n = p / 65;
        int l = p - n * 65;
        base1[r] = g_span_part + (size_t)n * DMODEL;
        if (l < LMAX) {
            int idx = s2c[n * LMAX + l];
            base2[r] = g_know_part + (size_t)idx * DMODEL;
        } else {
            base2[r] = g_sent_part + (size_t)n * DMODEL;
        }
    }

    float acc[8][8];
#pragma unroll
    for (int i = 0; i < 8; i++)
#pragma unroll
        for (int j = 0; j < 8; j++) acc[i][j] = 0.f;

    for (int k0 = 0; k0 < DMODEL; k0 += 16) {
#pragma unroll
        for (int r = 0; r < 2; r++) {
            float4 v1 = *(const float4*)(base1[r] + k0 + a_k);
            float4 v2 = *(const float4*)(base2[r] + k0 + a_k);
            int m = a_m + r * 64;
            As[a_k + 0][m] = fmaxf(v1.x + v2.x, 0.f);
            As[a_k + 1][m] = fmaxf(v1.y + v2.y, 0.f);
            As[a_k + 2][m] = fmaxf(v1.z + v2.z, 0.f);
            As[a_k + 3][m] = fmaxf(v1.w + v2.w, 0.f);
        }
#pragma unroll
        for (int r = 0; r < 2; r++) {
            int kk = b_k + r * 8;
            *(float4*)&Bs[kk][b_n] =
                *(const float4*)(g_W2p + (size_t)(k0 + kk) * DMODEL + n0 + b_n);
        }
        __syncthreads();
#pragma unroll
        for (int kk = 0; kk < 16; kk++) {
            float a[8], b[8];
            *(float4*)&a[0] = *(const float4*)&As[kk][ty * 8];
            *(float4*)&a[4] = *(const float4*)&As[kk][ty * 8 + 4];
            *(float4*)&b[0] = *(const float4*)&Bs[kk][tx * 8];
            *(float4*)&b[4] = *(const float4*)&Bs[kk][tx * 8 + 4];
#pragma unroll
            for (int i = 0; i < 8; i++)
#pragma unroll
                for (int j = 0; j < 8; j++) acc[i][j] += a[i] * b[j];
        }
        __syncthreads();
    }

    // epilogue: h2 = relu(acc + b2), partial score = sum h2 * w3
    int nb = n0 + tx * 8;
    float bb[8], ww[8];
#pragma unroll
    for (int j = 0; j < 8; j++) { bb[j] = g_b2p[nb + j]; ww[j] = g_w3p[nb + j]; }
#pragma unroll
    for (int i = 0; i < 8; i++) {
        float s = 0.f;
#pragma unroll
        for (int j = 0; j < 8; j++)
            s += fmaxf(acc[i][j] + bb[j], 0.f) * ww[j];
        sred[ty * 8 + i][tx] = s;
    }
    __syncthreads();
    if (tid < 128) {
        float s = 0.f;
#pragma unroll
        for (int q = 0; q < 16; q++) s += sred[tid][q];
        g_scpart[blockIdx.x * NPAIR + m0 + tid] = s;
    }
}

// ---------------- softmax + feature aggregation ----------------
__global__ void __launch_bounds__(128) softmax_features_kernel(
    const int* __restrict__ s2c, const int* __restrict__ lengths,
    const float* __restrict__ know, float* __restrict__ out) {
    int n = blockIdx.x;
    int t = threadIdx.x;
    __shared__ float sc[65];
    __shared__ const float* eptr[65];
    __shared__ float redmax, redinv;

    if (t < 65) {
        float s = 0.f;
#pragma unroll
        for (int q = 0; q < 4; q++) s += g_scpart[q * NPAIR + n * 65 + t];
        bool valid;
        const float* ep;
        if (t < LMAX) {
            int len = lengths[n];
            if (len < 1) len = 1;
            valid = t < len;
            int idx = s2c[n * LMAX + t];
            ep = know + (size_t)idx * DMODEL;
        } else {
            valid = true;
            ep = g_sentinel + (size_t)n * DMODEL;
        }
        sc[t] = valid ? s : -1e30f;
        eptr[t] = ep;
    }
    __syncthreads();
    if (t == 0) {
        float m = sc[0];
        for (int l = 1; l < 65; l++) m = fmaxf(m, sc[l]);
        redmax = m;
    }
    __syncthreads();
    float m = redmax;
    if (t < 65) sc[t] = expf(sc[t] - m);
    __syncthreads();
    if (t == 0) {
        float s = 0.f;
        for (int l = 0; l < 65; l++) s += sc[l];
        redinv = 1.f / s;
    }
    __syncthreads();
    if (t < 65) {
        sc[t] *= redinv;
        out[NSPAN * DMODEL + n * 65 + t] = sc[t];   // probs
    }
    __syncthreads();
    float a0 = 0.f, a1 = 0.f, a2 = 0.f, a3 = 0.f;
    for (int l = 0; l < 65; l++) {
        float p = sc[l];
        const float* ep = eptr[l];
        a0 += p * ep[t];
        a1 += p * ep[t + 128];
        a2 += p * ep[t + 256];
        a3 += p * ep[t + 384];
    }
    out[n * DMODEL + t]       = a0;   // features
    out[n * DMODEL + t + 128] = a1;
    out[n * DMODEL + t + 256] = a2;
    out[n * DMODEL + t + 384] = a3;
}

// ---------------- launch ----------------
extern "C" void kernel_launch(void* const* d_in, const int* in_sizes, int n_in,
                              void* d_out, int out_size) {
    const float* span    = (const float*)d_in[0];
    const float* know    = (const float*)d_in[1];
    const int*   s2c     = (const int*)d_in[2];
    const int*   lengths = (const int*)d_in[3];
    const float* Ws      = (const float*)d_in[4];
    const float* bs      = (const float*)d_in[5];
    const float* W1      = (const float*)d_in[6];
    const float* b1      = (const float*)d_in[7];
    const float* W2      = (const float*)d_in[8];
    const float* b2      = (const float*)d_in[9];
    const float* W3      = (const float*)d_in[10];
    // d_in[11] = b3: softmax-invariant constant shift, intentionally unused.
    float* out = (float*)d_out;

    float *p_sent, *p_spanp, *p_knowp, *p_sentp;
    cudaGetSymbolAddress((void**)&p_sent,  g_sentinel);
    cudaGetSymbolAddress((void**)&p_spanp, g_span_part);
    cudaGetSymbolAddress((void**)&p_knowp, g_know_part);
    cudaGetSymbolAddress((void**)&p_sentp, g_sent_part);

    prep_kernel<<<(DMODEL * DMODEL) / 256, 256>>>(W2, b2, W3);
    // sentinel = relu(span @ Ws + bs)
    gemm64_kernel<<<dim3(8, 4), 128>>>(span, Ws, DMODEL, bs, p_sent, DMODEL, 1);
    // span_part = span @ W1a + b1
    gemm64_kernel<<<dim3(8, 4), 128>>>(span, W1, HID, b1, p_spanp, HID, 0);
    // know_part = know @ W1b
    gemm64_kernel<<<dim3(8, 16), 128>>>(know, W1 + DMODEL * HID, HID, nullptr, p_knowp, HID, 0);
    // sent_part = sentinel @ W1b
    gemm64_kernel<<<dim3(8, 4), 128>>>(p_sent, W1 + DMODEL * HID, HID, nullptr, p_sentp, HID, 0);
    // fused h1 -> h2 -> score partials for the 16640 gathered pairs
    gemm_pair_kernel<<<dim3(4, 130), 256>>>(s2c);
    // softmax + features
    softmax_features_kernel<<<NSPAN, 128>>>(s2c, lengths, know, out);
}

// round 3
// speedup vs baseline: 1.5874x; 1.5874x over previous
#include <cuda_runtime.h>
#include <cstdint>

#define NSPAN  256
#define KKNOW  1024
#define DMODEL 512
#define LMAX   64
#define HID    500
#define NPAIR  (NSPAN * (LMAX + 1))   /* 16640 = 130 * 128 */

// ---------------- scratch (device globals; no allocation) ----------------
__device__ float g_sentinel[NSPAN * DMODEL];
__device__ float g_span_part[NSPAN * DMODEL];   // includes b1, cols [500,512)=0
__device__ float g_know_part[KKNOW * DMODEL];
__device__ float g_sent_part[NSPAN * DMODEL];
__device__ float g_W2t[DMODEL * DMODEL];        // W2 transposed+padded, tf32-rounded: [n][k]
__device__ float g_b2p[DMODEL];
__device__ float g_w3p[DMODEL];
__device__ float g_scpart[4 * NPAIR];           // per-N-tile score partials

__device__ __forceinline__ uint32_t f2tf32(float x) {
    uint32_t r;
    asm("cvt.rna.tf32.f32 %0, %1;" : "=r"(r) : "f"(x));
    return r;
}

__device__ __forceinline__ void mma_tf32(float* c,
                                         uint32_t a0, uint32_t a1, uint32_t a2, uint32_t a3,
                                         uint32_t b0, uint32_t b1) {
    asm volatile(
        "mma.sync.aligned.m16n8k8.row.col.f32.tf32.tf32.f32 "
        "{%0,%1,%2,%3}, {%4,%5,%6,%7}, {%8,%9}, {%0,%1,%2,%3};"
        : "+f"(c[0]), "+f"(c[1]), "+f"(c[2]), "+f"(c[3])
        : "r"(a0), "r"(a1), "r"(a2), "r"(a3), "r"(b0), "r"(b1));
}

// ---------------- prep: transpose/pad W2 (tf32-rounded), pad b2/W3 ----------------
__global__ void prep_kernel(const float* __restrict__ W2,
                            const float* __restrict__ b2,
                            const float* __restrict__ W3) {
    int i = blockIdx.x * blockDim.x + threadIdx.x;   // 0 .. 512*512
    int n = i >> 9, k = i & 511;
    float v = (k < HID && n < HID) ? W2[k * HID + n] : 0.f;
    g_W2t[i] = __uint_as_float(f2tf32(v));   // [n][k], rna-rounded to tf32
    if (i < DMODEL) {
        g_b2p[i] = (i < HID) ? b2[i] : 0.f;
        g_w3p[i] = (i < HID) ? W3[i] : 0.f;
    }
}

// ---------------- small SGEMM body: C[Mx512] = maybe_relu(A @ B[512xN] + bias)
__device__ __forceinline__ void gemm64_body(
    const float* __restrict__ A, const float* __restrict__ B, int ldb,
    const float* __restrict__ bias, float* __restrict__ C,
    int N, int relu) {
    __shared__ float As[16][64];
    __shared__ float Bs[16][64];
    int tid = threadIdx.x;
    int tx = tid & 7, ty = tid >> 3;
    int m0 = blockIdx.y * 64;
    int n0 = blockIdx.x * 64;
    int a_m = tid >> 1, a_k = (tid & 1) * 8;
    int b_k = tid >> 3, b_n = (tid & 7) * 8;

    float acc[4][8];
#pragma unroll
    for (int i = 0; i < 4; i++)
#pragma unroll
        for (int j = 0; j < 8; j++) acc[i][j] = 0.f;

    for (int k0 = 0; k0 < DMODEL; k0 += 16) {
        const float* ap = A + (size_t)(m0 + a_m) * DMODEL + k0 + a_k;
        float4 v0 = *(const float4*)ap;
        float4 v1 = *(const float4*)(ap + 4);
        As[a_k + 0][a_m] = v0.x; As[a_k + 1][a_m] = v0.y;
        As[a_k + 2][a_m] = v0.z; As[a_k + 3][a_m] = v0.w;
        As[a_k + 4][a_m] = v1.x; As[a_k + 5][a_m] = v1.y;
        As[a_k + 6][a_m] = v1.z; As[a_k + 7][a_m] = v1.w;
#pragma unroll
        for (int r = 0; r < 8; r += 4) {
            int n = n0 + b_n + r;
            float4 v = make_float4(0.f, 0.f, 0.f, 0.f);
            if (n < N) v = *(const float4*)(B + (size_t)(k0 + b_k) * ldb + n);
            *(float4*)&Bs[b_k][b_n + r] = v;
        }
        __syncthreads();
#pragma unroll
        for (int kk = 0; kk < 16; kk++) {
            float a[4], b[8];
            *(float4*)&a[0] = *(const float4*)&As[kk][ty * 4];
            *(float4*)&b[0] = *(const float4*)&Bs[kk][tx * 8];
            *(float4*)&b[4] = *(const float4*)&Bs[kk][tx * 8 + 4];
#pragma unroll
            for (int i = 0; i < 4; i++)
#pragma unroll
                for (int j = 0; j < 8; j++) acc[i][j] += a[i] * b[j];
        }
        __syncthreads();
    }
#pragma unroll
    for (int i = 0; i < 4; i++) {
        int m = m0 + ty * 4 + i;
#pragma unroll
        for (int j = 0; j < 8; j++) {
            int n = n0 + tx * 8 + j;
            float v = 0.f;
            if (n < N) {
                v = acc[i][j] + (bias ? bias[n] : 0.f);
                if (relu) v = fmaxf(v, 0.f);
            }
            C[(size_t)m * DMODEL + n] = v;
        }
    }
}

// three independent small GEMMs fused via blockIdx.z
__global__ void __launch_bounds__(128) gemm64_multi_kernel(
    const float* __restrict__ span, const float* __restrict__ know,
    const float* __restrict__ Ws, const float* __restrict__ bs,
    const float* __restrict__ W1, const float* __restrict__ b1) {
    int z = blockIdx.z;
    if (z < 2 && blockIdx.y >= 4) return;
    if (z == 0)      gemm64_body(span, Ws, DMODEL, bs, g_sentinel, DMODEL, 1);
    else if (z == 1) gemm64_body(span, W1, HID, b1, g_span_part, HID, 0);
    else             gemm64_body(know, W1 + DMODEL * HID, HID, nullptr, g_know_part, HID, 0);
}

__global__ void __launch_bounds__(128) gemm64_sent_kernel(const float* __restrict__ W1) {
    gemm64_body(g_sentinel, W1 + DMODEL * HID, HID, nullptr, g_sent_part, HID, 0);
}

// ================= tf32 mma.sync pair GEMM =================
// Per CTA: 128 pair-rows x 128 cols, K=512 in 32 chunks of 16.
// A[p][k] = relu(span_part[n][k] + {know_part[idx] | sent_part[n]}[k]).
// Epilogue folds relu(acc + b2)*w3 into per-row score partials.
// 256 threads = 8 warps arranged 4(M) x 2(N); warp tile 32x64.
#define APITCH 20
__global__ void __launch_bounds__(256) pair_mma_kernel(const int* __restrict__ s2c) {
    __shared__ uint32_t As[128][APITCH];
    __shared__ uint32_t Bs[128][APITCH];
    __shared__ const float* rowp1[128];
    __shared__ const float* rowp2[128];
    __shared__ float sred[128][2];

    int tid = threadIdx.x;
    int wid = tid >> 5, lane = tid & 31;
    int gid = lane >> 2, tig = lane & 3;
    int wm = wid >> 1, wn = wid & 1;          // 4 x 2 warp grid
    int m0 = blockIdx.y * 128;
    int n0 = blockIdx.x * 128;

    if (tid < 128) {
        int p = m0 + tid;
        int n = p / 65;
        int l = p - n * 65;
        rowp1[tid] = g_span_part + (size_t)n * DMODEL;
        rowp2[tid] = (l < LMAX)
            ? g_know_part + (size_t)s2c[n * LMAX + l] * DMODEL
            : g_sent_part + (size_t)n * DMODEL;
    }
    __syncthreads();

    int frow = tid >> 1;              // fill row (0..127)
    int fh = (tid & 1) * 8;           // half of the 16-wide chunk
    const float* arp1 = rowp1[frow] + fh;
    const float* arp2 = rowp2[frow] + fh;
    const float* brp  = g_W2t + (size_t)(n0 + frow) * DMODEL + fh;

    float acc[2][8][4];
#pragma unroll
    for (int mi = 0; mi < 2; mi++)
#pragma unroll
        for (int ni = 0; ni < 8; ni++)
#pragma unroll
            for (int q = 0; q < 4; q++) acc[mi][ni][q] = 0.f;

    float4 pa1[2], pa2[2], pb[2];
    // preload chunk 0
    pa1[0] = *(const float4*)(arp1);     pa1[1] = *(const float4*)(arp1 + 4);
    pa2[0] = *(const float4*)(arp2);     pa2[1] = *(const float4*)(arp2 + 4);
    pb[0]  = *(const float4*)(brp);      pb[1]  = *(const float4*)(brp + 4);

#pragma unroll 1
    for (int s = 0; s < 32; ++s) {
        // store prefetched regs to smem (with relu/add/cvt for A)
        {
            uint32_t av[8];
#pragma unroll
            for (int q = 0; q < 4; q++) {
                av[q]     = f2tf32(fmaxf(((const float*)&pa1[0])[q] + ((const float*)&pa2[0])[q], 0.f));
                av[q + 4] = f2tf32(fmaxf(((const float*)&pa1[1])[q] + ((const float*)&pa2[1])[q], 0.f));
            }
            *(uint4*)&As[frow][fh]     = *(uint4*)&av[0];
            *(uint4*)&As[frow][fh + 4] = *(uint4*)&av[4];
            *(uint4*)&Bs[frow][fh]     = *(uint4*)&pb[0];
            *(uint4*)&Bs[frow][fh + 4] = *(uint4*)&pb[1];
        }
        __syncthreads();

        // prefetch next chunk
        if (s + 1 < 32) {
            int k0 = (s + 1) * 16;
            pa1[0] = *(const float4*)(arp1 + k0);     pa1[1] = *(const float4*)(arp1 + k0 + 4);
            pa2[0] = *(const float4*)(arp2 + k0);     pa2[1] = *(const float4*)(arp2 + k0 + 4);
            pb[0]  = *(const float4*)(brp + k0);      pb[1]  = *(const float4*)(brp + k0 + 4);
        }

        // compute 2 k-steps of 8
#pragma unroll
        for (int ks = 0; ks < 2; ++ks) {
            int k = ks * 8;
            uint32_t af[2][4];
#pragma unroll
            for (int mi = 0; mi < 2; mi++) {
                int r = wm * 32 + mi * 16 + gid;
                af[mi][0] = As[r][k + tig];
                af[mi][1] = As[r + 8][k + tig];
                af[mi][2] = As[r][k + tig + 4];
                af[mi][3] = As[r + 8][k + tig + 4];
            }
#pragma unroll
            for (int ni = 0; ni < 8; ni++) {
                int nr = wn * 64 + ni * 8 + gid;
                uint32_t b0 = Bs[nr][k + tig];
                uint32_t b1 = Bs[nr][k + tig + 4];
                mma_tf32(acc[0][ni], af[0][0], af[0][1], af[0][2], af[0][3], b0, b1);
                mma_tf32(acc[1][ni], af[1][0], af[1][1], af[1][2], af[1][3], b0, b1);
            }
        }
        __syncthreads();
    }

    // epilogue: per-row partial score over this CTA's 128 cols
#pragma unroll
    for (int mi = 0; mi < 2; mi++) {
        float p0 = 0.f, p1 = 0.f;   // rows (base+gid) and (base+gid+8)
#pragma unroll
        for (int ni = 0; ni < 8; ni++) {
            int n = n0 + wn * 64 + ni * 8 + 2 * tig;
            float b2a = g_b2p[n],     w3a = g_w3p[n];
            float b2b = g_b2p[n + 1], w3b = g_w3p[n + 1];
            p0 += fmaxf(acc[mi][ni][0] + b2a, 0.f) * w3a
                + fmaxf(acc[mi][ni][1] + b2b, 0.f) * w3b;
            p1 += fmaxf(acc[mi][ni][2] + b2a, 0.f) * w3a
                + fmaxf(acc[mi][ni][3] + b2b, 0.f) * w3b;
        }
        // reduce over tig (4 lanes)
        p0 += __shfl_xor_sync(0xFFFFFFFFu, p0, 1);
        p0 += __shfl_xor_sync(0xFFFFFFFFu, p0, 2);
        p1 += __shfl_xor_sync(0xFFFFFFFFu, p1, 1);
        p1 += __shfl_xor_sync(0xFFFFFFFFu, p1, 2);
        if (tig == 0) {
            int r = wm * 32 + mi * 16 + gid;
            sred[r][wn] = p0;
            sred[r + 8][wn] = p1;
        }
        __syncthreads();
    }
    if (tid < 128)
        g_scpart[blockIdx.x * NPAIR + m0 + tid] = sred[tid][0] + sred[tid][1];
}

// ---------------- softmax + feature aggregation ----------------
__global__ void __launch_bounds__(128) softmax_features_kernel(
    const int* __restrict__ s2c, const int* __restrict__ lengths,
    const float* __restrict__ know, float* __restrict__ out) {
    int n = blockIdx.x;
    int t = threadIdx.x;
    __shared__ float sc[65];
    __shared__ const float* eptr[65];
    __shared__ float redmax, redinv;

    if (t < 65) {
        float s = 0.f;
#pragma unroll
        for (int q = 0; q < 4; q++) s += g_scpart[q * NPAIR + n * 65 + t];
        bool valid;
        const float* ep;
        if (t < LMAX) {
            int len = lengths[n];
            if (len < 1) len = 1;
            valid = t < len;
            int idx = s2c[n * LMAX + t];
            ep = know + (size_t)idx * DMODEL;
        } else {
            valid = true;
            ep = g_sentinel + (size_t)n * DMODEL;
        }
        sc[t] = valid ? s : -1e30f;
        eptr[t] = ep;
    }
    __syncthreads();
    if (t == 0) {
        float m = sc[0];
        for (int l = 1; l < 65; l++) m = fmaxf(m, sc[l]);
        redmax = m;
    }
    __syncthreads();
    float m = redmax;
    if (t < 65) sc[t] = expf(sc[t] - m);
    __syncthreads();
    if (t == 0) {
        float s = 0.f;
        for (int l = 0; l < 65; l++) s += sc[l];
        redinv = 1.f / s;
    }
    __syncthreads();
    if (t < 65) {
        sc[t] *= redinv;
        out[NSPAN * DMODEL + n * 65 + t] = sc[t];   // probs
    }
    __syncthreads();
    float a0 = 0.f, a1 = 0.f, a2 = 0.f, a3 = 0.f;
    for (int l = 0; l < 65; l++) {
        float p = sc[l];
        const float* ep = eptr[l];
        a0 += p * ep[t];
        a1 += p * ep[t + 128];
        a2 += p * ep[t + 256];
        a3 += p * ep[t + 384];
    }
    out[n * DMODEL + t]       = a0;   // features
    out[n * DMODEL + t + 128] = a1;
    out[n * DMODEL + t + 256] = a2;
    out[n * DMODEL + t + 384] = a3;
}

// ---------------- launch ----------------
extern "C" void kernel_launch(void* const* d_in, const int* in_sizes, int n_in,
                              void* d_out, int out_size) {
    const float* span    = (const float*)d_in[0];
    const float* know    = (const float*)d_in[1];
    const int*   s2c     = (const int*)d_in[2];
    const int*   lengths = (const int*)d_in[3];
    const float* Ws      = (const float*)d_in[4];
    const float* bs      = (const float*)d_in[5];
    const float* W1      = (const float*)d_in[6];
    const float* b1      = (const float*)d_in[7];
    const float* W2      = (const float*)d_in[8];
    const float* b2      = (const float*)d_in[9];
    const float* W3      = (const float*)d_in[10];
    // d_in[11] = b3: softmax-invariant constant shift, intentionally unused.
    float* out = (float*)d_out;

    prep_kernel<<<(DMODEL * DMODEL) / 256, 256>>>(W2, b2, W3);
    // sentinel / span_part / know_part concurrently
    gemm64_multi_kernel<<<dim3(8, 16, 3), 128>>>(span, know, Ws, bs, W1, b1);
    // sent_part = sentinel @ W1b (depends on sentinel)
    gemm64_sent_kernel<<<dim3(8, 4), 128>>>(W1);
    // fused h1 -> h2 -> score partials (tf32 mma.sync)
    pair_mma_kernel<<<dim3(4, 130), 256>>>(s2c);
    // softmax + features
    softmax_features_kernel<<<NSPAN, 128>>>(s2c, lengths, know, out);
}

// round 4
// speedup vs baseline: 1.7791x; 1.1208x over previous
#include <cuda_runtime.h>
#include <cstdint>

#define NSPAN  256
#define KKNOW  1024
#define DMODEL 512
#define LMAX   64
#define HID    500
#define NPAIR  (NSPAN * (LMAX + 1))   /* 16640 = 130 * 128 */

// ---------------- scratch (device globals; no allocation) ----------------
__device__ float g_sentinel[NSPAN * DMODEL];
__device__ float g_span_part[NSPAN * DMODEL];   // includes b1, cols [500,512)=0
__device__ float g_know_part[KKNOW * DMODEL];
__device__ float g_sent_part[NSPAN * DMODEL];
__device__ float g_W2t[DMODEL * DMODEL];        // W2 transposed+padded, tf32-rounded: [n][k]
__device__ float g_b2p[DMODEL];
__device__ float g_w3p[DMODEL];
__device__ float g_scpart[4 * NPAIR];           // per-N-tile score partials

__device__ __forceinline__ uint32_t f2tf32(float x) {
    uint32_t r;
    asm("cvt.rna.tf32.f32 %0, %1;" : "=r"(r) : "f"(x));
    return r;
}
__device__ __forceinline__ uint32_t smem_u32(const void* p) {
    uint32_t a;
    asm("{ .reg .u64 t; cvta.to.shared.u64 t, %1; cvt.u32.u64 %0, t; }"
        : "=r"(a) : "l"(p));
    return a;
}
__device__ __forceinline__ void mma_tf32(float* c,
                                         uint32_t a0, uint32_t a1, uint32_t a2, uint32_t a3,
                                         uint32_t b0, uint32_t b1) {
    asm volatile(
        "mma.sync.aligned.m16n8k8.row.col.f32.tf32.tf32.f32 "
        "{%0,%1,%2,%3}, {%4,%5,%6,%7}, {%8,%9}, {%0,%1,%2,%3};"
        : "+f"(c[0]), "+f"(c[1]), "+f"(c[2]), "+f"(c[3])
        : "r"(a0), "r"(a1), "r"(a2), "r"(a3), "r"(b0), "r"(b1));
}
#define CP_ASYNC16(dst, src) \
    asm volatile("cp.async.cg.shared.global [%0], [%1], 16;" \
                 :: "r"(dst), "l"(src) : "memory")
#define CP_COMMIT() asm volatile("cp.async.commit_group;" ::: "memory")
#define CP_WAIT(n)  asm volatile("cp.async.wait_group %0;" :: "n"(n) : "memory")

// ---------------- prep: transpose/pad W2 (tf32-rounded), pad b2/W3 ----------------
__global__ void prep_kernel(const float* __restrict__ W2,
                            const float* __restrict__ b2,
                            const float* __restrict__ W3) {
    int i = blockIdx.x * blockDim.x + threadIdx.x;   // 0 .. 512*512
    int n = i >> 9, k = i & 511;
    float v = (k < HID && n < HID) ? W2[k * HID + n] : 0.f;
    g_W2t[i] = __uint_as_float(f2tf32(v));   // [n][k]
    if (i < DMODEL) {
        g_b2p[i] = (i < HID) ? b2[i] : 0.f;
        g_w3p[i] = (i < HID) ? W3[i] : 0.f;
    }
}

// ================= small tf32 mma GEMM =================
// C[(m0..m0+128) x 512] = maybe_relu(A[..x512] @ B[512 x N](row-major,ldb) + bias)
// 128 threads = 4 warps (2M x 2N), warp tile 64x64. Cols >= N written as 0.
#define PITCH 20
__device__ __forceinline__ void mma_gemm_body(
    const float* __restrict__ A, const float* __restrict__ B, int ldb,
    const float* __restrict__ bias, float* __restrict__ C, int N, int relu) {
    __shared__ uint32_t As[128 * PITCH];
    __shared__ uint32_t Bs[128 * PITCH];
    const int tid = threadIdx.x;
    const int lane = tid & 31, wid = tid >> 5;
    const int gid = lane >> 2, tig = lane & 3;
    const int wm = wid >> 1, wn = wid & 1;
    const int m0 = blockIdx.y * 128, n0 = blockIdx.x * 128;

    const float* arow = A + (size_t)(m0 + tid) * DMODEL;
    const bool nok = (n0 + tid) < N;
    const float* bcol = B + (size_t)(n0 + tid);

    float acc[4][8][4];
#pragma unroll
    for (int mi = 0; mi < 4; mi++)
#pragma unroll
        for (int ni = 0; ni < 8; ni++)
#pragma unroll
            for (int q = 0; q < 4; q++) acc[mi][ni][q] = 0.f;

    for (int k0 = 0; k0 < DMODEL; k0 += 16) {
        __syncthreads();
#pragma unroll
        for (int i = 0; i < 4; i++) {
            float4 v = *(const float4*)(arow + k0 + i * 4);
            uint4 o;
            o.x = f2tf32(v.x); o.y = f2tf32(v.y);
            o.z = f2tf32(v.z); o.w = f2tf32(v.w);
            *(uint4*)&As[tid * PITCH + i * 4] = o;
        }
#pragma unroll
        for (int kk = 0; kk < 16; kk++) {
            float v = nok ? bcol[(size_t)(k0 + kk) * ldb] : 0.f;
            Bs[tid * PITCH + kk] = f2tf32(v);
        }
        __syncthreads();
#pragma unroll
        for (int ks = 0; ks < 2; ks++) {
            int kk = ks * 8 + tig;
            uint32_t a[4][4];
#pragma unroll
            for (int mi = 0; mi < 4; mi++) {
                int r = wm * 64 + mi * 16 + gid;
                a[mi][0] = As[r * PITCH + kk];
                a[mi][1] = As[(r + 8) * PITCH + kk];
                a[mi][2] = As[r * PITCH + kk + 4];
                a[mi][3] = As[(r + 8) * PITCH + kk + 4];
            }
#pragma unroll
            for (int ni = 0; ni < 8; ni++) {
                int nr = wn * 64 + ni * 8 + gid;
                uint32_t b0 = Bs[nr * PITCH + kk];
                uint32_t b1 = Bs[nr * PITCH + kk + 4];
#pragma unroll
                for (int mi = 0; mi < 4; mi++)
                    mma_tf32(acc[mi][ni], a[mi][0], a[mi][1], a[mi][2], a[mi][3], b0, b1);
            }
        }
    }
    // epilogue
#pragma unroll
    for (int mi = 0; mi < 4; mi++) {
        int r = m0 + wm * 64 + mi * 16 + gid;
#pragma unroll
        for (int ni = 0; ni < 8; ni++) {
            int nn = n0 + wn * 64 + ni * 8 + 2 * tig;
            float ba = (bias && nn < N) ? bias[nn] : 0.f;
            float bb = (bias && nn + 1 < N) ? bias[nn + 1] : 0.f;
            float c0 = (nn < N) ? acc[mi][ni][0] + ba : 0.f;
            float c1 = (nn + 1 < N) ? acc[mi][ni][1] + bb : 0.f;
            float c2 = (nn < N) ? acc[mi][ni][2] + ba : 0.f;
            float c3 = (nn + 1 < N) ? acc[mi][ni][3] + bb : 0.f;
            if (relu) {
                c0 = fmaxf(c0, 0.f); c1 = fmaxf(c1, 0.f);
                c2 = fmaxf(c2, 0.f); c3 = fmaxf(c3, 0.f);
            }
            *(float2*)&C[(size_t)r * DMODEL + nn] = make_float2(c0, c1);
            *(float2*)&C[(size_t)(r + 8) * DMODEL + nn] = make_float2(c2, c3);
        }
    }
}

__global__ void __launch_bounds__(128) mma_gemm_multi_kernel(
    const float* __restrict__ span, const float* __restrict__ know,
    const float* __restrict__ Ws, const float* __restrict__ bs,
    const float* __restrict__ W1, const float* __restrict__ b1) {
    int z = blockIdx.z;
    if (z < 2 && blockIdx.y >= 2) return;
    if (z == 0)      mma_gemm_body(span, Ws, DMODEL, bs, g_sentinel, DMODEL, 1);
    else if (z == 1) mma_gemm_body(span, W1, HID, b1, g_span_part, HID, 0);
    else             mma_gemm_body(know, W1 + DMODEL * HID, HID, nullptr, g_know_part, HID, 0);
}

__global__ void __launch_bounds__(128) mma_gemm_sent_kernel(const float* __restrict__ W1) {
    mma_gemm_body(g_sentinel, W1 + DMODEL * HID, HID, nullptr, g_sent_part, HID, 0);
}

// ================= tf32 mma pair GEMM (pipelined) =================
// CTA: 128 pair-rows x 128 cols, K=512 in 32 chunks of 16.
// 4 warps (2M x 2N), warp tile 64x64. A: reg-prefetch + relu/add/cvt -> smem (2 bufs).
// B (g_W2t, [n][k]): cp.async.cg, 3 bufs. One __syncthreads per chunk.
// smem words: As0=0, As1=2560, Bs0=5120, Bs1=7680, Bs2=10240, sred=12800..13056
#define PAIR_SMEM_BYTES (13056 * 4)
__global__ void __launch_bounds__(128) pair_mma_kernel(const int* __restrict__ s2c) {
    extern __shared__ uint32_t sm[];
    uint32_t* Asb[2] = { sm, sm + 2560 };
    uint32_t* Bsb[3] = { sm + 5120, sm + 7680, sm + 10240 };
    float* sred = (float*)(sm + 12800);

    const int tid = threadIdx.x;
    const int lane = tid & 31, wid = tid >> 5;
    const int gid = lane >> 2, tig = lane & 3;
    const int wm = wid >> 1, wn = wid & 1;
    const int m0 = blockIdx.y * 128, n0 = blockIdx.x * 128;

    {   // row pointers for this thread's fill row (row = tid)
    }
    int p = m0 + tid, nsp = p / 65, l = p - nsp * 65;
    const float* arp1 = g_span_part + (size_t)nsp * DMODEL;
    const float* arp2 = (l < LMAX)
        ? g_know_part + (size_t)s2c[nsp * LMAX + l] * DMODEL
        : g_sent_part + (size_t)nsp * DMODEL;
    const float* brp = g_W2t + (size_t)(n0 + tid) * DMODEL;

    uint32_t su = smem_u32(sm);
    uint32_t bdst[3];
#pragma unroll
    for (int q = 0; q < 3; q++) bdst[q] = su + (5120 + q * 2560 + tid * PITCH) * 4;

    float acc[4][8][4];
#pragma unroll
    for (int mi = 0; mi < 4; mi++)
#pragma unroll
        for (int ni = 0; ni < 8; ni++)
#pragma unroll
            for (int q = 0; q < 4; q++) acc[mi][ni][q] = 0.f;

    float4 pa1[4], pa2[4];

#define LDA(s) do { int _k = (s) * 16;                                        \
    _Pragma("unroll") for (int i = 0; i < 4; i++) {                           \
        pa1[i] = *(const float4*)(arp1 + _k + i * 4);                         \
        pa2[i] = *(const float4*)(arp2 + _k + i * 4); } } while (0)

#define STA(bufi) do { uint32_t* _d = Asb[bufi];                              \
    _Pragma("unroll") for (int i = 0; i < 4; i++) {                           \
        uint4 o;                                                              \
        o.x = f2tf32(fmaxf(pa1[i].x + pa2[i].x, 0.f));                        \
        o.y = f2tf32(fmaxf(pa1[i].y + pa2[i].y, 0.f));                        \
        o.z = f2tf32(fmaxf(pa1[i].z + pa2[i].z, 0.f));                        \
        o.w = f2tf32(fmaxf(pa1[i].w + pa2[i].w, 0.f));                        \
        *(uint4*)&_d[tid * PITCH + i * 4] = o; } } while (0)

#define LDB(s, q) do { int _k = (s) * 16;                                     \
    _Pragma("unroll") for (int i = 0; i < 4; i++)                             \
        CP_ASYNC16(bdst[q] + i * 16, brp + _k + i * 4);                       \
    CP_COMMIT(); } while (0)

    // prologue
    LDA(0);
    STA(0);
    LDB(0, 0);
    LDA(1);
    LDB(1, 1);
    CP_WAIT(1);          // chunk0 B done
    __syncthreads();     // As0 + Bs0 visible

#pragma unroll 1
    for (int s = 0; s < 32; ++s) {
        int buf = s & 1;
        if (s + 1 < 32) STA(buf ^ 1);                 // store chunk s+1 (from pa regs)
        if (s + 2 < 32) { LDA(s + 2); LDB(s + 2, (s + 2) % 3); }
        if (s + 1 < 32) { if (s + 2 < 32) CP_WAIT(1); else CP_WAIT(0); }

        const uint32_t* A_ = Asb[buf];
        const uint32_t* B_ = Bsb[s % 3];
#pragma unroll
        for (int ks = 0; ks < 2; ks++) {
            int kk = ks * 8 + tig;
            uint32_t a[4][4];
#pragma unroll
            for (int mi = 0; mi < 4; mi++) {
                int r = wm * 64 + mi * 16 + gid;
                a[mi][0] = A_[r * PITCH + kk];
                a[mi][1] = A_[(r + 8) * PITCH + kk];
                a[mi][2] = A_[r * PITCH + kk + 4];
                a[mi][3] = A_[(r + 8) * PITCH + kk + 4];
            }
#pragma unroll
            for (int ni = 0; ni < 8; ni++) {
                int nr = wn * 64 + ni * 8 + gid;
                uint32_t b0 = B_[nr * PITCH + kk];
                uint32_t b1 = B_[nr * PITCH + kk + 4];
#pragma unroll
                for (int mi = 0; mi < 4; mi++)
                    mma_tf32(acc[mi][ni], a[mi][0], a[mi][1], a[mi][2], a[mi][3], b0, b1);
            }
        }
        __syncthreads();
    }

    // epilogue: score partial = sum_n relu(acc + b2) * w3 over this CTA's 128 cols
#pragma unroll
    for (int mi = 0; mi < 4; mi++) {
        float p0 = 0.f, p1 = 0.f;
#pragma unroll
        for (int ni = 0; ni < 8; ni++) {
            int nn = n0 + wn * 64 + ni * 8 + 2 * tig;
            float b2a = g_b2p[nn],     w3a = g_w3p[nn];
            float b2b = g_b2p[nn + 1], w3b = g_w3p[nn + 1];
            p0 += fmaxf(acc[mi][ni][0] + b2a, 0.f) * w3a
                + fmaxf(acc[mi][ni][1] + b2b, 0.f) * w3b;
            p1 += fmaxf(acc[mi][ni][2] + b2a, 0.f) * w3a
                + fmaxf(acc[mi][ni][3] + b2b, 0.f) * w3b;
        }
        p0 += __shfl_xor_sync(0xFFFFFFFFu, p0, 1);
        p0 += __shfl_xor_sync(0xFFFFFFFFu, p0, 2);
        p1 += __shfl_xor_sync(0xFFFFFFFFu, p1, 1);
        p1 += __shfl_xor_sync(0xFFFFFFFFu, p1, 2);
        if (tig == 0) {
            int r = wm * 64 + mi * 16 + gid;
            sred[r * 2 + wn] = p0;
            sred[(r + 8) * 2 + wn] = p1;
        }
    }
    __syncthreads();
    if (tid < 128)
        g_scpart[blockIdx.x * NPAIR + m0 + tid] = sred[tid * 2] + sred[tid * 2 + 1];
#undef LDA
#undef STA
#undef LDB
}

// ---------------- softmax + feature aggregation ----------------
__global__ void __launch_bounds__(128) softmax_features_kernel(
    const int* __restrict__ s2c, const int* __restrict__ lengths,
    const float* __restrict__ know, float* __restrict__ out) {
    int n = blockIdx.x;
    int t = threadIdx.x;
    __shared__ float sc[65];
    __shared__ const float* eptr[65];
    __shared__ float redmax, redinv;

    if (t < 65) {
        float s = 0.f;
#pragma unroll
        for (int q = 0; q < 4; q++) s += g_scpart[q * NPAIR + n * 65 + t];
        bool valid;
        const float* ep;
        if (t < LMAX) {
            int len = lengths[n];
            if (len < 1) len = 1;
            valid = t < len;
            int idx = s2c[n * LMAX + t];
            ep = know + (size_t)idx * DMODEL;
        } else {
            valid = true;
            ep = g_sentinel + (size_t)n * DMODEL;
        }
        sc[t] = valid ? s : -1e30f;
        eptr[t] = ep;
    }
    __syncthreads();
    if (t == 0) {
        float m = sc[0];
        for (int l = 1; l < 65; l++) m = fmaxf(m, sc[l]);
        redmax = m;
    }
    __syncthreads();
    float m = redmax;
    if (t < 65) sc[t] = expf(sc[t] - m);
    __syncthreads();
    if (t == 0) {
        float s = 0.f;
        for (int l = 0; l < 65; l++) s += sc[l];
        redinv = 1.f / s;
    }
    __syncthreads();
    if (t < 65) {
        sc[t] *= redinv;
        out[NSPAN * DMODEL + n * 65 + t] = sc[t];   // probs
    }
    __syncthreads();
    float a0 = 0.f, a1 = 0.f, a2 = 0.f, a3 = 0.f;
    for (int l = 0; l < 65; l++) {
        float p = sc[l];
        const float* ep = eptr[l];
        a0 += p * ep[t];
        a1 += p * ep[t + 128];
        a2 += p * ep[t + 256];
        a3 += p * ep[t + 384];
    }
    out[n * DMODEL + t]       = a0;   // features
    out[n * DMODEL + t + 128] = a1;
    out[n * DMODEL + t + 256] = a2;
    out[n * DMODEL + t + 384] = a3;
}

// ---------------- launch ----------------
extern "C" void kernel_launch(void* const* d_in, const int* in_sizes, int n_in,
                              void* d_out, int out_size) {
    const float* span    = (const float*)d_in[0];
    const float* know    = (const float*)d_in[1];
    const int*   s2c     = (const int*)d_in[2];
    const int*   lengths = (const int*)d_in[3];
    const float* Ws      = (const float*)d_in[4];
    const float* bs      = (const float*)d_in[5];
    const float* W1      = (const float*)d_in[6];
    const float* b1      = (const float*)d_in[7];
    const float* W2      = (const float*)d_in[8];
    const float* b2      = (const float*)d_in[9];
    const float* W3      = (const float*)d_in[10];
    // d_in[11] = b3: softmax-invariant constant shift, intentionally unused.
    float* out = (float*)d_out;

    static int configured = 0;
    if (!configured) {
        cudaFuncSetAttribute(pair_mma_kernel,
                             cudaFuncAttributeMaxDynamicSharedMemorySize,
                             PAIR_SMEM_BYTES);
        configured = 1;
    }

    prep_kernel<<<(DMODEL * DMODEL) / 256, 256>>>(W2, b2, W3);
    // sentinel / span_part / know_part concurrently (tf32 mma)
    mma_gemm_multi_kernel<<<dim3(4, 8, 3), 128>>>(span, know, Ws, bs, W1, b1);
    // sent_part = sentinel @ W1b (depends on sentinel)
    mma_gemm_sent_kernel<<<dim3(4, 2), 128>>>(W1);
    // fused h1 -> h2 -> score partials (pipelined tf32 mma)
    pair_mma_kernel<<<dim3(4, 130), 128, PAIR_SMEM_BYTES>>>(s2c);
    // softmax + features
    softmax_features_kernel<<<NSPAN, 128>>>(s2c, lengths, know, out);
}

// round 5
// speedup vs baseline: 2.2339x; 1.2556x over previous
#include <cuda_runtime.h>
#include <cstdint>

#define NSPAN  256
#define KKNOW  1024
#define DMODEL 512
#define LMAX   64
#define HID    500
#define NPAIR  (NSPAN * (LMAX + 1))   /* 16640 = 130 * 128 */

// ---------------- scratch (device globals; no allocation) ----------------
__device__ float g_sentinel[NSPAN * DMODEL];
__device__ float g_span_part[NSPAN * DMODEL];   // includes b1, cols [500,512)=0
__device__ float g_know_part[KKNOW * DMODEL];
__device__ float g_sent_part[NSPAN * DMODEL];
__device__ float g_W2t[DMODEL * DMODEL];        // W2^T, tf32, pair-permuted k
__device__ float g_WsT[DMODEL * DMODEL];        // Ws^T, tf32, pair-permuted k
__device__ float g_W1aT[DMODEL * DMODEL];       // W1a^T
__device__ float g_W1bT[DMODEL * DMODEL];       // W1b^T
__device__ float g_b2p[DMODEL];
__device__ float g_w3p[DMODEL];
__device__ float g_scpart[4 * NPAIR];           // per-N-tile score partials

__device__ __forceinline__ uint32_t f2tf32(float x) {
    uint32_t r;
    asm("cvt.rna.tf32.f32 %0, %1;" : "=r"(r) : "f"(x));
    return r;
}
__device__ __forceinline__ uint32_t smem_u32(const void* p) {
    uint32_t a;
    asm("{ .reg .u64 t; cvta.to.shared.u64 t, %1; cvt.u32.u64 %0, t; }"
        : "=r"(a) : "l"(p));
    return a;
}
__device__ __forceinline__ void mma_tf32(float* c,
                                         uint32_t a0, uint32_t a1, uint32_t a2, uint32_t a3,
                                         uint32_t b0, uint32_t b1) {
    asm volatile(
        "mma.sync.aligned.m16n8k8.row.col.f32.tf32.tf32.f32 "
        "{%0,%1,%2,%3}, {%4,%5,%6,%7}, {%8,%9}, {%0,%1,%2,%3};"
        : "+f"(c[0]), "+f"(c[1]), "+f"(c[2]), "+f"(c[3])
        : "r"(a0), "r"(a1), "r"(a2), "r"(a3), "r"(b0), "r"(b1));
}
#define CP_ASYNC16(dst, src) \
    asm volatile("cp.async.cg.shared.global [%0], [%1], 16;" \
                 :: "r"(dst), "l"(src) : "memory")
#define CP_COMMIT() asm volatile("cp.async.commit_group;" ::: "memory")
#define CP_WAIT(n)  asm volatile("cp.async.wait_group %0;" :: "n"(n) : "memory")

// pair-permutation within each 16-word k block: word = (c&3)*2 + ((c>>2)&1) + (c&8)
// => (x[kk], x[kk+4]) are adjacent words at offset tig*2 + ks*8.
#define PERMC(c) ((((c) & 3) << 1) + (((c) >> 2) & 1) + ((c) & 8))

// smem word layout (dynamic):
//   As: 2 bufs of 128*24 @ 0, 3072
//   Bs: 3 bufs of 128*24 @ 6144, 9216, 12288
//   sred: 256 floats @ 15360
#define APITCH 24
#define SMEM_WORDS (15360 + 256)
#define SMEM_BYTES (SMEM_WORDS * 4)

// ---------------- prep: transpose+tf32+permute all B matrices, pad b2/w3 ----
__global__ void prep_kernel(const float* __restrict__ W2,
                            const float* __restrict__ Ws,
                            const float* __restrict__ W1,
                            const float* __restrict__ b2,
                            const float* __restrict__ W3) {
    int i = blockIdx.x * blockDim.x + threadIdx.x;   // 0 .. 512*512-1
    int k = i >> 9, n = i & 511;
    int z = blockIdx.y;
    float v;
    float* dst;
    if (z == 0)      { v = (k < HID && n < HID) ? W2[k * HID + n] : 0.f; dst = g_W2t; }
    else if (z == 1) { v = Ws[k * DMODEL + n];                           dst = g_WsT; }
    else if (z == 2) { v = (n < HID) ? W1[k * HID + n] : 0.f;            dst = g_W1aT; }
    else             { v = (n < HID) ? W1[(k + DMODEL) * HID + n] : 0.f; dst = g_W1bT; }
    dst[n * DMODEL + (k & ~15) + PERMC(k & 15)] = __uint_as_float(f2tf32(v));
    if (z == 0 && i < DMODEL) {
        g_b2p[i] = (i < HID) ? b2[i] : 0.f;
        g_w3p[i] = (i < HID) ? W3[i] : 0.f;
    }
}

// ================= unified pipelined tf32 mma GEMM core =================
// CTA tile 128(M) x 128(N), K=512 in 32 chunks of 16.
// 256 threads = 8 warps (4M x 2N), warp tile 32x64, acc[2][8][4].
// A: reg prefetch (+relu/add for PAIR) -> permuted smem (2 bufs).
// B: cp.async from pre-permuted global (3 bufs).
template<bool PAIR>
__device__ __forceinline__ void gemm_core(
    const float* __restrict__ arp1, const float* __restrict__ arp2,
    const float* __restrict__ Bt,
    const float* __restrict__ bias, float* __restrict__ C, int N, int relu) {
    extern __shared__ uint32_t sm[];
    const int tid = threadIdx.x;
    const int lane = tid & 31, wid = tid >> 5;
    const int gid = lane >> 2, tig = lane & 3;
    const int wm = wid >> 1, wn = wid & 1;        // 4M x 2N warps
    const int m0 = blockIdx.y * 128, n0 = blockIdx.x * 128;
    const int arow = tid >> 1, ah = (tid & 1) * 8;

    const float* brp = Bt + (size_t)(n0 + arow) * DMODEL + ah;
    arp1 += ah;
    arp2 += ah;

    uint32_t su = smem_u32(sm);
    uint32_t bdst[3];
#pragma unroll
    for (int q = 0; q < 3; q++)
        bdst[q] = su + (uint32_t)(6144 + q * 3072 + arow * APITCH + ah) * 4;

    float acc[2][8][4];
#pragma unroll
    for (int mi = 0; mi < 2; mi++)
#pragma unroll
        for (int ni = 0; ni < 8; ni++)
#pragma unroll
            for (int q = 0; q < 4; q++) acc[mi][ni][q] = 0.f;

    float4 pa1[2], pa2[2];

#define LDA(s) do { int _k = (s) * 16;                                        \
    pa1[0] = *(const float4*)(arp1 + _k);                                     \
    pa1[1] = *(const float4*)(arp1 + _k + 4);                                 \
    if (PAIR) {                                                               \
        pa2[0] = *(const float4*)(arp2 + _k);                                 \
        pa2[1] = *(const float4*)(arp2 + _k + 4);                             \
    } } while (0)

#define STA(b) do {                                                           \
    uint32_t* _d = sm + (b) * 3072 + arow * APITCH + ah;                      \
    float w0, w1, w2, w3, w4, w5, w6, w7;                                     \
    if (PAIR) {                                                               \
        w0 = fmaxf(pa1[0].x + pa2[0].x, 0.f);                                 \
        w1 = fmaxf(pa1[0].y + pa2[0].y, 0.f);                                 \
        w2 = fmaxf(pa1[0].z + pa2[0].z, 0.f);                                 \
        w3 = fmaxf(pa1[0].w + pa2[0].w, 0.f);                                 \
        w4 = fmaxf(pa1[1].x + pa2[1].x, 0.f);                                 \
        w5 = fmaxf(pa1[1].y + pa2[1].y, 0.f);                                 \
        w6 = fmaxf(pa1[1].z + pa2[1].z, 0.f);                                 \
        w7 = fmaxf(pa1[1].w + pa2[1].w, 0.f);                                 \
    } else {                                                                  \
        w0 = pa1[0].x; w1 = pa1[0].y; w2 = pa1[0].z; w3 = pa1[0].w;           \
        w4 = pa1[1].x; w5 = pa1[1].y; w6 = pa1[1].z; w7 = pa1[1].w;           \
    }                                                                         \
    uint4 q0 = make_uint4(f2tf32(w0), f2tf32(w4), f2tf32(w1), f2tf32(w5));    \
    uint4 q1 = make_uint4(f2tf32(w2), f2tf32(w6), f2tf32(w3), f2tf32(w7));    \
    *(uint4*)&_d[0] = q0;                                                     \
    *(uint4*)&_d[4] = q1; } while (0)

#define LDB(s, q) do { int _k = (s) * 16;                                     \
    CP_ASYNC16(bdst[q], brp + _k);                                            \
    CP_ASYNC16(bdst[q] + 16, brp + _k + 4);                                   \
    CP_COMMIT(); } while (0)

    // prologue
    LDA(0); STA(0); LDB(0, 0);
    LDA(1); LDB(1, 1);
    CP_WAIT(1);
    __syncthreads();

#pragma unroll 1
    for (int s = 0; s < 32; ++s) {
        int buf = s & 1;
        if (s + 1 < 32) STA(buf ^ 1);
        if (s + 2 < 32) { LDA(s + 2); LDB(s + 2, (s + 2) % 3); CP_WAIT(1); }
        else            { CP_WAIT(0); }

        const uint32_t* A_ = sm + buf * 3072;
        const uint32_t* B_ = sm + 6144 + (s % 3) * 3072;
#pragma unroll
        for (int ks = 0; ks < 2; ks++) {
            int kko = ks * 8 + tig * 2;
            uint2 a[2][2];
#pragma unroll
            for (int mi = 0; mi < 2; mi++) {
                int r = wm * 32 + mi * 16 + gid;
                a[mi][0] = *(const uint2*)&A_[r * APITCH + kko];
                a[mi][1] = *(const uint2*)&A_[(r + 8) * APITCH + kko];
            }
#pragma unroll
            for (int ni = 0; ni < 8; ni++) {
                int nr = wn * 64 + ni * 8 + gid;
                uint2 b = *(const uint2*)&B_[nr * APITCH + kko];
#pragma unroll
                for (int mi = 0; mi < 2; mi++)
                    mma_tf32(acc[mi][ni],
                             a[mi][0].x, a[mi][1].x, a[mi][0].y, a[mi][1].y,
                             b.x, b.y);
            }
        }
        __syncthreads();
    }
#undef LDA
#undef STA
#undef LDB

    if (PAIR) {
        float* sred = (float*)(sm + 15360);
#pragma unroll
        for (int mi = 0; mi < 2; mi++) {
            float p0 = 0.f, p1 = 0.f;
#pragma unroll
            for (int ni = 0; ni < 8; ni++) {
                int nn = n0 + wn * 64 + ni * 8 + 2 * tig;
                float b2a = g_b2p[nn],     w3a = g_w3p[nn];
                float b2b = g_b2p[nn + 1], w3b = g_w3p[nn + 1];
                p0 += fmaxf(acc[mi][ni][0] + b2a, 0.f) * w3a
                    + fmaxf(acc[mi][ni][1] + b2b, 0.f) * w3b;
                p1 += fmaxf(acc[mi][ni][2] + b2a, 0.f) * w3a
                    + fmaxf(acc[mi][ni][3] + b2b, 0.f) * w3b;
            }
            p0 += __shfl_xor_sync(0xFFFFFFFFu, p0, 1);
            p0 += __shfl_xor_sync(0xFFFFFFFFu, p0, 2);
            p1 += __shfl_xor_sync(0xFFFFFFFFu, p1, 1);
            p1 += __shfl_xor_sync(0xFFFFFFFFu, p1, 2);
            if (tig == 0) {
                int r = wm * 32 + mi * 16 + gid;
                sred[r * 2 + wn] = p0;
                sred[(r + 8) * 2 + wn] = p1;
            }
        }
        __syncthreads();
        if (tid < 128)
            g_scpart[blockIdx.x * NPAIR + m0 + tid] = sred[tid * 2] + sred[tid * 2 + 1];
    } else {
#pragma unroll
        for (int mi = 0; mi < 2; mi++) {
            int r = m0 + wm * 32 + mi * 16 + gid;
#pragma unroll
            for (int ni = 0; ni < 8; ni++) {
                int nn = n0 + wn * 64 + ni * 8 + 2 * tig;
                float ba = (bias && nn < N) ? bias[nn] : 0.f;
                float bb = (bias && nn + 1 < N) ? bias[nn + 1] : 0.f;
                float c0 = (nn < N) ? acc[mi][ni][0] + ba : 0.f;
                float c1 = (nn + 1 < N) ? acc[mi][ni][1] + bb : 0.f;
                float c2 = (nn < N) ? acc[mi][ni][2] + ba : 0.f;
                float c3 = (nn + 1 < N) ? acc[mi][ni][3] + bb : 0.f;
                if (relu) {
                    c0 = fmaxf(c0, 0.f); c1 = fmaxf(c1, 0.f);
                    c2 = fmaxf(c2, 0.f); c3 = fmaxf(c3, 0.f);
                }
                *(float2*)&C[(size_t)r * DMODEL + nn] = make_float2(c0, c1);
                *(float2*)&C[(size_t)(r + 8) * DMODEL + nn] = make_float2(c2, c3);
            }
        }
    }
}

// ---------------- kernel wrappers ----------------
__global__ void __launch_bounds__(256, 2) pair_mma_kernel(const int* __restrict__ s2c) {
    int m0 = blockIdx.y * 128;
    int row = threadIdx.x >> 1;
    int p = m0 + row, nsp = p / 65, l = p - nsp * 65;
    const float* a1 = g_span_part + (size_t)nsp * DMODEL;
    const float* a2 = (l < LMAX)
        ? g_know_part + (size_t)s2c[nsp * LMAX + l] * DMODEL
        : g_sent_part + (size_t)nsp * DMODEL;
    gemm_core<true>(a1, a2, g_W2t, nullptr, nullptr, 0, 0);
}

__global__ void __launch_bounds__(256, 2) small_multi_kernel(
    const float* __restrict__ span, const float* __restrict__ know,
    const float* __restrict__ bs, const float* __restrict__ b1) {
    int z = blockIdx.z;
    if (z < 2 && blockIdx.y >= 2) return;
    const float* A; const float* Bt; const float* bias; float* C; int N; int relu;
    if (z == 0)      { A = span; Bt = g_WsT;  bias = bs;      C = g_sentinel;  N = DMODEL; relu = 1; }
    else if (z == 1) { A = span; Bt = g_W1aT; bias = b1;      C = g_span_part; N = HID;    relu = 0; }
    else             { A = know; Bt = g_W1bT; bias = nullptr; C = g_know_part; N = HID;    relu = 0; }
    const float* a1 = A + (size_t)(blockIdx.y * 128 + (threadIdx.x >> 1)) * DMODEL;
    gemm_core<false>(a1, a1, Bt, bias, C, N, relu);
}

__global__ void __launch_bounds__(256, 2) small_sent_kernel() {
    const float* a1 = g_sentinel + (size_t)(blockIdx.y * 128 + (threadIdx.x >> 1)) * DMODEL;
    gemm_core<false>(a1, a1, g_W1bT, nullptr, g_sent_part, HID, 0);
}

// ---------------- softmax + feature aggregation ----------------
__global__ void __launch_bounds__(128) softmax_features_kernel(
    const int* __restrict__ s2c, const int* __restrict__ lengths,
    const float* __restrict__ know, float* __restrict__ out) {
    int n = blockIdx.x;
    int t = threadIdx.x;
    __shared__ float sc[65];
    __shared__ const float* eptr[65];
    __shared__ float redmax, redinv;

    if (t < 65) {
        float s = 0.f;
#pragma unroll
        for (int q = 0; q < 4; q++) s += g_scpart[q * NPAIR + n * 65 + t];
        bool valid;
        const float* ep;
        if (t < LMAX) {
            int len = lengths[n];
            if (len < 1) len = 1;
            valid = t < len;
            int idx = s2c[n * LMAX + t];
            ep = know + (size_t)idx * DMODEL;
        } else {
            valid = true;
            ep = g_sentinel + (size_t)n * DMODEL;
        }
        sc[t] = valid ? s : -1e30f;
        eptr[t] = ep;
    }
    __syncthreads();
    if (t == 0) {
        float m = sc[0];
        for (int l = 1; l < 65; l++) m = fmaxf(m, sc[l]);
        redmax = m;
    }
    __syncthreads();
    float m = redmax;
    if (t < 65) sc[t] = expf(sc[t] - m);
    __syncthreads();
    if (t == 0) {
        float s = 0.f;
        for (int l = 0; l < 65; l++) s += sc[l];
        redinv = 1.f / s;
    }
    __syncthreads();
    if (t < 65) {
        sc[t] *= redinv;
        out[NSPAN * DMODEL + n * 65 + t] = sc[t];   // probs
    }
    __syncthreads();
    float a0 = 0.f, a1 = 0.f, a2 = 0.f, a3 = 0.f;
    for (int l = 0; l < 65; l++) {
        float p = sc[l];
        const float* ep = eptr[l];
        a0 += p * ep[t];
        a1 += p * ep[t + 128];
        a2 += p * ep[t + 256];
        a3 += p * ep[t + 384];
    }
    out[n * DMODEL + t]       = a0;   // features
    out[n * DMODEL + t + 128] = a1;
    out[n * DMODEL + t + 256] = a2;
    out[n * DMODEL + t + 384] = a3;
}

// ---------------- launch ----------------
extern "C" void kernel_launch(void* const* d_in, const int* in_sizes, int n_in,
                              void* d_out, int out_size) {
    const float* span    = (const float*)d_in[0];
    const float* know    = (const float*)d_in[1];
    const int*   s2c     = (const int*)d_in[2];
    const int*   lengths = (const int*)d_in[3];
    const float* Ws      = (const float*)d_in[4];
    const float* bs      = (const float*)d_in[5];
    const float* W1      = (const float*)d_in[6];
    const float* b1      = (const float*)d_in[7];
    const float* W2      = (const float*)d_in[8];
    const float* b2      = (const float*)d_in[9];
    const float* W3      = (const float*)d_in[10];
    // d_in[11] = b3: softmax-invariant constant shift, intentionally unused.
    float* out = (float*)d_out;

    cudaFuncSetAttribute(pair_mma_kernel,
                         cudaFuncAttributeMaxDynamicSharedMemorySize, SMEM_BYTES);
    cudaFuncSetAttribute(small_multi_kernel,
                         cudaFuncAttributeMaxDynamicSharedMemorySize, SMEM_BYTES);
    cudaFuncSetAttribute(small_sent_kernel,
                         cudaFuncAttributeMaxDynamicSharedMemorySize, SMEM_BYTES);

    // transpose+permute+tf32 all B matrices
    prep_kernel<<<dim3(1024, 4), 256>>>(W2, Ws, W1, b2, W3);
    // sentinel / span_part / know_part concurrently
    small_multi_kernel<<<dim3(4, 8, 3), 256, SMEM_BYTES>>>(span, know, bs, b1);
    // sent_part = sentinel @ W1b
    small_sent_kernel<<<dim3(4, 2), 256, SMEM_BYTES>>>();
    // fused h1 -> h2 -> score partials
    pair_mma_kernel<<<dim3(4, 130), 256, SMEM_BYTES>>>(s2c);
    // softmax + features
    softmax_features_kernel<<<NSPAN, 128>>>(s2c, lengths, know, out);
}

// round 6
// speedup vs baseline: 2.5494x; 1.1412x over previous
#include <cuda_runtime.h>
#include <cstdint>

#define NSPAN  256
#define KKNOW  1024
#define DMODEL 512
#define LMAX   64
#define HID    500
#define NPAIR  (NSPAN * (LMAX + 1))   /* 16640 = 130 * 128 */

// ---------------- scratch (device globals; no allocation) ----------------
__device__ float g_sentinel[NSPAN * DMODEL];
__device__ float g_span_part[NSPAN * DMODEL];   // includes b1, cols [500,512)=0
__device__ float g_know_part[KKNOW * DMODEL];
__device__ float g_sent_part[NSPAN * DMODEL];
__device__ float g_W2t[DMODEL * DMODEL];        // W2^T, tf32, 4-group permuted k
__device__ float g_WsT[DMODEL * DMODEL];        // Ws^T
__device__ float g_W1aT[DMODEL * DMODEL];       // W1a^T
__device__ float g_W1bT[DMODEL * DMODEL];       // W1b^T
__device__ float g_b2p[DMODEL];
__device__ float g_w3p[DMODEL];
__device__ float g_scpart[4 * NPAIR];           // per-N-tile score partials

__device__ __forceinline__ uint32_t f2tf32(float x) {
    uint32_t r;
    asm("cvt.rna.tf32.f32 %0, %1;" : "=r"(r) : "f"(x));
    return r;
}
__device__ __forceinline__ uint32_t smem_u32(const void* p) {
    uint32_t a;
    asm("{ .reg .u64 t; cvta.to.shared.u64 t, %1; cvt.u32.u64 %0, t; }"
        : "=r"(a) : "l"(p));
    return a;
}
__device__ __forceinline__ void mma_tf32(float* c,
                                         uint32_t a0, uint32_t a1, uint32_t a2, uint32_t a3,
                                         uint32_t b0, uint32_t b1) {
    asm volatile(
        "mma.sync.aligned.m16n8k8.row.col.f32.tf32.tf32.f32 "
        "{%0,%1,%2,%3}, {%4,%5,%6,%7}, {%8,%9}, {%0,%1,%2,%3};"
        : "+f"(c[0]), "+f"(c[1]), "+f"(c[2]), "+f"(c[3])
        : "r"(a0), "r"(a1), "r"(a2), "r"(a3), "r"(b0), "r"(b1));
}
#define CP_ASYNC16(dst, src) \
    asm volatile("cp.async.cg.shared.global [%0], [%1], 16;" \
                 :: "r"(dst), "l"(src) : "memory")
#define CP_COMMIT() asm volatile("cp.async.commit_group;" ::: "memory")
#define CP_WAIT(n)  asm volatile("cp.async.wait_group %0;" :: "n"(n) : "memory")

// A-side pair-permutation (pairs (k, k+4) adjacent) — STS.128 friendly
#define PERMC(c) ((((c) & 3) << 1) + (((c) >> 2) & 1) + ((c) & 8))
// B-side 4-group permutation ((k, k+4, k+8, k+12) adjacent) — LDS.128 fragments
#define PERMB(c) ((((c) & 3) << 2) | (((c) >> 2) & 3))

// smem word layout (dynamic):
//   As: 2 bufs of 128*24 @ 0, 3072      (pair-perm, PITCH 24, conflict-free)
//   Bs: 4 bufs of 128*16 @ 6144 + q*2048 (4-group perm, PITCH 16)
//   sred: 256 floats @ 14336
#define APITCH 24
#define SMEM_WORDS (14336 + 256)
#define SMEM_BYTES (SMEM_WORDS * 4)

// ---------------- prep: transpose+tf32+permute all B matrices, pad b2/w3 ----
__global__ void prep_kernel(const float* __restrict__ W2,
                            const float* __restrict__ Ws,
                            const float* __restrict__ W1,
                            const float* __restrict__ b2,
                            const float* __restrict__ W3) {
    int i = blockIdx.x * blockDim.x + threadIdx.x;   // 0 .. 512*512-1
    int k = i >> 9, n = i & 511;
    int z = blockIdx.y;
    float v;
    float* dst;
    if (z == 0)      { v = (k < HID && n < HID) ? W2[k * HID + n] : 0.f; dst = g_W2t; }
    else if (z == 1) { v = Ws[k * DMODEL + n];                           dst = g_WsT; }
    else if (z == 2) { v = (n < HID) ? W1[k * HID + n] : 0.f;            dst = g_W1aT; }
    else             { v = (n < HID) ? W1[(k + DMODEL) * HID + n] : 0.f; dst = g_W1bT; }
    dst[n * DMODEL + (k & ~15) + PERMB(k & 15)] = __uint_as_float(f2tf32(v));
    if (z == 0 && i < DMODEL) {
        g_b2p[i] = (i < HID) ? b2[i] : 0.f;
        g_w3p[i] = (i < HID) ? W3[i] : 0.f;
    }
}

// ================= unified pipelined tf32 mma GEMM core =================
// CTA tile 128(M) x 128(N), K=512 in 32 chunks of 16.
// 256 threads = 8 warps (4M x 2N), warp tile 32x64, acc[2][8][4].
// A: reg prefetch (+relu/add for PAIR), raw fp32 (HMMA truncates) -> smem (2 bufs)
// B: cp.async from pre-permuted global (4 bufs, static indices).
template<bool PAIR>
__device__ __forceinline__ void gemm_core(
    const float* __restrict__ arp1, const float* __restrict__ arp2,
    const float* __restrict__ Bt,
    const float* __restrict__ bias, float* __restrict__ C, int N, int relu) {
    extern __shared__ uint32_t sm[];
    const int tid = threadIdx.x;
    const int lane = tid & 31, wid = tid >> 5;
    const int gid = lane >> 2, tig = lane & 3;
    const int wm = wid >> 1, wn = wid & 1;        // 4M x 2N warps
    const int m0 = blockIdx.y * 128, n0 = blockIdx.x * 128;
    const int arow = tid >> 1, ah = (tid & 1) * 8;

    const float* brp = Bt + (size_t)(n0 + arow) * DMODEL + ah;
    arp1 += ah;
    arp2 += ah;

    uint32_t su = smem_u32(sm);
    uint32_t bdst[4];
#pragma unroll
    for (int q = 0; q < 4; q++)
        bdst[q] = su + (uint32_t)(6144 + q * 2048 + arow * 16 + ah) * 4;

    float acc[2][8][4];
#pragma unroll
    for (int mi = 0; mi < 2; mi++)
#pragma unroll
        for (int ni = 0; ni < 8; ni++)
#pragma unroll
            for (int q = 0; q < 4; q++) acc[mi][ni][q] = 0.f;

    float4 pa1[2], pa2[2];

#define LDA(s) do { int _k = (s) * 16;                                        \
    pa1[0] = *(const float4*)(arp1 + _k);                                     \
    pa1[1] = *(const float4*)(arp1 + _k + 4);                                 \
    if (PAIR) {                                                               \
        pa2[0] = *(const float4*)(arp2 + _k);                                 \
        pa2[1] = *(const float4*)(arp2 + _k + 4);                             \
    } } while (0)

#define STA(b) do {                                                           \
    uint32_t* _d = sm + (b) * 3072 + arow * APITCH + ah;                      \
    float w0, w1, w2, w3, w4, w5, w6, w7;                                     \
    if (PAIR) {                                                               \
        w0 = fmaxf(pa1[0].x + pa2[0].x, 0.f);                                 \
        w1 = fmaxf(pa1[0].y + pa2[0].y, 0.f);                                 \
        w2 = fmaxf(pa1[0].z + pa2[0].z, 0.f);                                 \
        w3 = fmaxf(pa1[0].w + pa2[0].w, 0.f);                                 \
        w4 = fmaxf(pa1[1].x + pa2[1].x, 0.f);                                 \
        w5 = fmaxf(pa1[1].y + pa2[1].y, 0.f);                                 \
        w6 = fmaxf(pa1[1].z + pa2[1].z, 0.f);                                 \
        w7 = fmaxf(pa1[1].w + pa2[1].w, 0.f);                                 \
    } else {                                                                  \
        w0 = pa1[0].x; w1 = pa1[0].y; w2 = pa1[0].z; w3 = pa1[0].w;           \
        w4 = pa1[1].x; w5 = pa1[1].y; w6 = pa1[1].z; w7 = pa1[1].w;           \
    }                                                                         \
    uint4 q0 = make_uint4(__float_as_uint(w0), __float_as_uint(w4),           \
                          __float_as_uint(w1), __float_as_uint(w5));          \
    uint4 q1 = make_uint4(__float_as_uint(w2), __float_as_uint(w6),           \
                          __float_as_uint(w3), __float_as_uint(w7));          \
    *(uint4*)&_d[0] = q0;                                                     \
    *(uint4*)&_d[4] = q1; } while (0)

// always commits (possibly-empty group) so CP_WAIT counts stay static
#define LDB(s, q) do { if ((s) < 32) { int _k = (s) * 16;                     \
        CP_ASYNC16(bdst[q], brp + _k);                                        \
        CP_ASYNC16(bdst[q] + 16, brp + _k + 4); }                             \
    CP_COMMIT(); } while (0)

#define COMPUTE(AB, BB) do {                                                  \
    const uint32_t* A_ = sm + (AB) * 3072;                                    \
    const uint32_t* B_ = sm + 6144 + (BB) * 2048;                             \
    uint2 aa[2][2][2];                                                        \
    _Pragma("unroll") for (int ks = 0; ks < 2; ks++)                          \
    _Pragma("unroll") for (int mi = 0; mi < 2; mi++) {                        \
        int r = wm * 32 + mi * 16 + gid;                                      \
        int kko = ks * 8 + tig * 2;                                           \
        aa[ks][mi][0] = *(const uint2*)&A_[r * APITCH + kko];                 \
        aa[ks][mi][1] = *(const uint2*)&A_[(r + 8) * APITCH + kko];           \
    }                                                                         \
    _Pragma("unroll") for (int ni = 0; ni < 8; ni++) {                        \
        int nr = wn * 64 + ni * 8 + gid;                                      \
        uint4 b = *(const uint4*)&B_[nr * 16 + tig * 4];                      \
        mma_tf32(acc[0][ni], aa[0][0][0].x, aa[0][0][1].x,                    \
                 aa[0][0][0].y, aa[0][0][1].y, b.x, b.y);                     \
        mma_tf32(acc[1][ni], aa[0][1][0].x, aa[0][1][1].x,                    \
                 aa[0][1][0].y, aa[0][1][1].y, b.x, b.y);                     \
        mma_tf32(acc[0][ni], aa[1][0][0].x, aa[1][0][1].x,                    \
                 aa[1][0][0].y, aa[1][0][1].y, b.z, b.w);                     \
        mma_tf32(acc[1][ni], aa[1][1][0].x, aa[1][1][1].x,                    \
                 aa[1][1][0].y, aa[1][1][1].y, b.z, b.w);                     \
    } } while (0)

#define ITER(s, AB, BB) do {                                                  \
    if ((s) + 1 < 32) STA((AB) ^ 1);                                          \
    if ((s) + 2 < 32) LDA((s) + 2);                                           \
    LDB((s) + 3, ((BB) + 3) & 3);                                             \
    CP_WAIT(2);                                                               \
    COMPUTE(AB, BB);                                                          \
    __syncthreads(); } while (0)

    // prologue: chunk0 -> A0, B groups 0..2 in flight, chunk1 in regs
    LDA(0); STA(0);
    LDB(0, 0); LDB(1, 1); LDB(2, 2);
    LDA(1);
    CP_WAIT(2);
    __syncthreads();

    // main: s = 0..27 (all guards true), static buffer indices
#pragma unroll 1
    for (int s0 = 0; s0 < 28; s0 += 4) {
        ITER(s0 + 0, 0, 0);
        ITER(s0 + 1, 1, 1);
        ITER(s0 + 2, 0, 2);
        ITER(s0 + 3, 1, 3);
    }
    // tail: s = 28..31
    ITER(28, 0, 0);
    ITER(29, 1, 1);
    ITER(30, 0, 2);
    ITER(31, 1, 3);

#undef LDA
#undef STA
#undef LDB
#undef COMPUTE
#undef ITER

    if (PAIR) {
        float* sred = (float*)(sm + 14336);
#pragma unroll
        for (int mi = 0; mi < 2; mi++) {
            float p0 = 0.f, p1 = 0.f;
#pragma unroll
            for (int ni = 0; ni < 8; ni++) {
                int nn = n0 + wn * 64 + ni * 8 + 2 * tig;
                float b2a = g_b2p[nn],     w3a = g_w3p[nn];
                float b2b = g_b2p[nn + 1], w3b = g_w3p[nn + 1];
                p0 += fmaxf(acc[mi][ni][0] + b2a, 0.f) * w3a
                    + fmaxf(acc[mi][ni][1] + b2b, 0.f) * w3b;
                p1 += fmaxf(acc[mi][ni][2] + b2a, 0.f) * w3a
                    + fmaxf(acc[mi][ni][3] + b2b, 0.f) * w3b;
            }
            p0 += __shfl_xor_sync(0xFFFFFFFFu, p0, 1);
            p0 += __shfl_xor_sync(0xFFFFFFFFu, p0, 2);
            p1 += __shfl_xor_sync(0xFFFFFFFFu, p1, 1);
            p1 += __shfl_xor_sync(0xFFFFFFFFu, p1, 2);
            if (tig == 0) {
                int r = wm * 32 + mi * 16 + gid;
                sred[r * 2 + wn] = p0;
                sred[(r + 8) * 2 + wn] = p1;
            }
        }
        __syncthreads();
        if (tid < 128)
            g_scpart[blockIdx.x * NPAIR + m0 + tid] = sred[tid * 2] + sred[tid * 2 + 1];
    } else {
#pragma unroll
        for (int mi = 0; mi < 2; mi++) {
            int r = m0 + wm * 32 + mi * 16 + gid;
#pragma unroll
            for (int ni = 0; ni < 8; ni++) {
                int nn = n0 + wn * 64 + ni * 8 + 2 * tig;
                float ba = (bias && nn < N) ? bias[nn] : 0.f;
                float bb = (bias && nn + 1 < N) ? bias[nn + 1] : 0.f;
                float c0 = (nn < N) ? acc[mi][ni][0] + ba : 0.f;
                float c1 = (nn + 1 < N) ? acc[mi][ni][1] + bb : 0.f;
                float c2 = (nn < N) ? acc[mi][ni][2] + ba : 0.f;
                float c3 = (nn + 1 < N) ? acc[mi][ni][3] + bb : 0.f;
                if (relu) {
                    c0 = fmaxf(c0, 0.f); c1 = fmaxf(c1, 0.f);
                    c2 = fmaxf(c2, 0.f); c3 = fmaxf(c3, 0.f);
                }
                *(float2*)&C[(size_t)r * DMODEL + nn] = make_float2(c0, c1);
                *(float2*)&C[(size_t)(r + 8) * DMODEL + nn] = make_float2(c2, c3);
            }
        }
    }
}

// ---------------- kernel wrappers ----------------
__global__ void __launch_bounds__(256, 2) pair_mma_kernel(const int* __restrict__ s2c) {
    int m0 = blockIdx.y * 128;
    int row = threadIdx.x >> 1;
    int p = m0 + row, nsp = p / 65, l = p - nsp * 65;
    const float* a1 = g_span_part + (size_t)nsp * DMODEL;
    const float* a2 = (l < LMAX)
        ? g_know_part + (size_t)s2c[nsp * LMAX + l] * DMODEL
        : g_sent_part + (size_t)nsp * DMODEL;
    gemm_core<true>(a1, a2, g_W2t, nullptr, nullptr, 0, 0);
}

__global__ void __launch_bounds__(256, 2) small_multi_kernel(
    const float* __restrict__ span, const float* __restrict__ know,
    const float* __restrict__ bs, const float* __restrict__ b1) {
    int z = blockIdx.z;
    if (z < 2 && blockIdx.y >= 2) return;
    const float* A; const float* Bt; const float* bias; float* C; int N; int relu;
    if (z == 0)      { A = span; Bt = g_WsT;  bias = bs;      C = g_sentinel;  N = DMODEL; relu = 1; }
    else if (z == 1) { A = span; Bt = g_W1aT; bias = b1;      C = g_span_part; N = HID;    relu = 0; }
    else             { A = know; Bt = g_W1bT; bias = nullptr; C = g_know_part; N = HID;    relu = 0; }
    const float* a1 = A + (size_t)(blockIdx.y * 128 + (threadIdx.x >> 1)) * DMODEL;
    gemm_core<false>(a1, a1, Bt, bias, C, N, relu);
}

__global__ void __launch_bounds__(256, 2) small_sent_kernel() {
    const float* a1 = g_sentinel + (size_t)(blockIdx.y * 128 + (threadIdx.x >> 1)) * DMODEL;
    gemm_core<false>(a1, a1, g_W1bT, nullptr, g_sent_part, HID, 0);
}

// ---------------- softmax + feature aggregation ----------------
__global__ void __launch_bounds__(128) softmax_features_kernel(
    const int* __restrict__ s2c, const int* __restrict__ lengths,
    const float* __restrict__ know, float* __restrict__ out) {
    int n = blockIdx.x;
    int t = threadIdx.x;
    __shared__ float sc[65];
    __shared__ const float* eptr[65];
    __shared__ float redmax, redinv;

    if (t < 65) {
        float s = 0.f;
#pragma unroll
        for (int q = 0; q < 4; q++) s += g_scpart[q * NPAIR + n * 65 + t];
        bool valid;
        const float* ep;
        if (t < LMAX) {
            int len = lengths[n];
            if (len < 1) len = 1;
            valid = t < len;
            int idx = s2c[n * LMAX + t];
            ep = know + (size_t)idx * DMODEL;
        } else {
            valid = true;
            ep = g_sentinel + (size_t)n * DMODEL;
        }
        sc[t] = valid ? s : -1e30f;
        eptr[t] = ep;
    }
    __syncthreads();
    if (t == 0) {
        float m = sc[0];
        for (int l = 1; l < 65; l++) m = fmaxf(m, sc[l]);
        redmax = m;
    }
    __syncthreads();
    float m = redmax;
    if (t < 65) sc[t] = expf(sc[t] - m);
    __syncthreads();
    if (t == 0) {
        float s = 0.f;
        for (int l = 0; l < 65; l++) s += sc[l];
        redinv = 1.f / s;
    }
    __syncthreads();
    if (t < 65) {
        sc[t] *= redinv;
        out[NSPAN * DMODEL + n * 65 + t] = sc[t];   // probs
    }
    __syncthreads();
    float a0 = 0.f, a1 = 0.f, a2 = 0.f, a3 = 0.f;
    for (int l = 0; l < 65; l++) {
        float p = sc[l];
        const float* ep = eptr[l];
        a0 += p * ep[t];
        a1 += p * ep[t + 128];
        a2 += p * ep[t + 256];
        a3 += p * ep[t + 384];
    }
    out[n * DMODEL + t]       = a0;   // features
    out[n * DMODEL + t + 128] = a1;
    out[n * DMODEL + t + 256] = a2;
    out[n * DMODEL + t + 384] = a3;
}

// ---------------- launch ----------------
extern "C" void kernel_launch(void* const* d_in, const int* in_sizes, int n_in,
                              void* d_out, int out_size) {
    const float* span    = (const float*)d_in[0];
    const float* know    = (const float*)d_in[1];
    const int*   s2c     = (const int*)d_in[2];
    const int*   lengths = (const int*)d_in[3];
    const float* Ws      = (const float*)d_in[4];
    const float* bs      = (const float*)d_in[5];
    const float* W1      = (const float*)d_in[6];
    const float* b1      = (const float*)d_in[7];
    const float* W2      = (const float*)d_in[8];
    const float* b2      = (const float*)d_in[9];
    const float* W3      = (const float*)d_in[10];
    // d_in[11] = b3: softmax-invariant constant shift, intentionally unused.
    float* out = (float*)d_out;

    cudaFuncSetAttribute(pair_mma_kernel,
                         cudaFuncAttributeMaxDynamicSharedMemorySize, SMEM_BYTES);
    cudaFuncSetAttribute(small_multi_kernel,
                         cudaFuncAttributeMaxDynamicSharedMemorySize, SMEM_BYTES);
    cudaFuncSetAttribute(small_sent_kernel,
                         cudaFuncAttributeMaxDynamicSharedMemorySize, SMEM_BYTES);

    // transpose+permute+tf32 all B matrices
    prep_kernel<<<dim3(1024, 4), 256>>>(W2, Ws, W1, b2, W3);
    // sentinel / span_part / know_part concurrently
    small_multi_kernel<<<dim3(4, 8, 3), 256, SMEM_BYTES>>>(span, know, bs, b1);
    // sent_part = sentinel @ W1b
    small_sent_kernel<<<dim3(4, 2), 256, SMEM_BYTES>>>();
    // fused h1 -> h2 -> score partials
    pair_mma_kernel<<<dim3(4, 130), 256, SMEM_BYTES>>>(s2c);
    // softmax + features
    softmax_features_kernel<<<NSPAN, 128>>>(s2c, lengths, know, out);
}